// round 1
// baseline (speedup 1.0000x reference)
#include <cuda_runtime.h>
#include <cstdint>
#include <cstddef>

// ---------------------------------------------------------------------------
// GraphSAGE 3-layer forward, fp32.
// Strategy:
//   * Aggregation is linear => transform-then-aggregate:
//       mean(h[src]) @ Wn == segment_sum((h@Wn)[src]) * inv_deg
//   * One GEMM per layer computes BOTH h@Ws (+bias) -> S and h@Wn -> Y
//     (concatenated output tile; A loaded once).
//   * Edge scatter: per edge, S[dst] += inv_deg[dst] * Y[src] using
//     red.global.add.v4.f32 (vectorized no-return reduction, sm_90+).
//   * ReLU fused into the next layer's GEMM A-load.
//   * Layer 2 (C=47) padded to 48 cols; final kernel strips padding.
// ---------------------------------------------------------------------------

#define NMAX 100000

// Scratch (static device globals: allowed; runtime allocation is not)
__device__ float g_SA[(size_t)NMAX * 128];
__device__ float g_SB[(size_t)NMAX * 128];
__device__ float g_Yb[(size_t)NMAX * 128];
__device__ float g_inv[NMAX];
__device__ int   g_deg[NMAX];

// ---------------------------------------------------------------------------
__global__ void deg_zero_kernel(int* __restrict__ deg, int n) {
    int i = blockIdx.x * blockDim.x + threadIdx.x;
    if (i < n) deg[i] = 0;
}

__global__ void deg_count_kernel(int* __restrict__ deg, const int* __restrict__ dst, int e) {
    int i = blockIdx.x * blockDim.x + threadIdx.x;
    if (i < e) atomicAdd(&deg[dst[i]], 1);
}

__global__ void deg_inv_kernel(const int* __restrict__ deg, float* __restrict__ inv, int n) {
    int i = blockIdx.x * blockDim.x + threadIdx.x;
    if (i < n) {
        int d = deg[i];
        inv[i] = 1.0f / (float)(d > 1 ? d : 1);
    }
}

// ---------------------------------------------------------------------------
// Fused dual-output GEMM:
//   S[m, j] = (relu?)A[m,:] @ Ws[:, j] + bias[j]   for j < HP   (padded to HP)
//   Y[m, j] = (relu?)A[m,:] @ Wn[:, j]             for j < HP
// A is [n, 128] row-major; Ws/Wn are [128, WCOLS] row-major.
// Tile: BM=64 rows x BN=2*HP cols, K=128 in BK=16 chunks. 256 threads,
// each thread owns a 4-row x TN-col microtile; columns STRIDED by 16 so
// epilogue stores coalesce.
// ---------------------------------------------------------------------------
template<int HP, int WCOLS, bool RELU>
__global__ __launch_bounds__(256) void gemm_dual_kernel(
    const float* __restrict__ A, int n,
    const float* __restrict__ Ws, const float* __restrict__ Wn,
    const float* __restrict__ bias,
    float* __restrict__ S, float* __restrict__ Y)
{
    constexpr int BM = 64;
    constexpr int BK = 16;
    constexpr int BN = 2 * HP;        // 256 or 96
    constexpr int TN = BN / 16;       // 16 or 6
    constexpr int K  = 128;

    __shared__ float As[BK][BM];      // transposed A tile
    __shared__ float Bs[BK][BN];

    const int tid  = threadIdx.x;
    const int m0   = blockIdx.x * BM;
    const int trow = tid >> 4;        // 0..15
    const int tcol = tid & 15;        // 0..15

    float acc[4][TN];
    #pragma unroll
    for (int r = 0; r < 4; r++)
        #pragma unroll
        for (int c = 0; c < TN; c++)
            acc[r][c] = 0.0f;

    for (int kt = 0; kt < K; kt += BK) {
        // --- load A tile (float4 per thread), transpose into smem ---
        {
            int r  = tid >> 2;            // 0..63
            int kq = (tid & 3) * 4;       // 0,4,8,12
            int gr = m0 + r;
            float4 v = make_float4(0.f, 0.f, 0.f, 0.f);
            if (gr < n)
                v = *reinterpret_cast<const float4*>(A + (size_t)gr * K + kt + kq);
            if (RELU) {
                v.x = fmaxf(v.x, 0.f); v.y = fmaxf(v.y, 0.f);
                v.z = fmaxf(v.z, 0.f); v.w = fmaxf(v.w, 0.f);
            }
            As[kq + 0][r] = v.x;
            As[kq + 1][r] = v.y;
            As[kq + 2][r] = v.z;
            As[kq + 3][r] = v.w;
        }
        // --- load B tile: [Ws | Wn], zero-padded beyond WCOLS ---
        #pragma unroll
        for (int i = 0; i < (BK * BN) / 256; i++) {
            int idx = tid + i * 256;
            int k   = idx / BN;
            int j   = idx - k * BN;
            float w;
            if (j < HP) {
                w = (j < WCOLS) ? Ws[(size_t)(kt + k) * WCOLS + j] : 0.0f;
            } else {
                int jj = j - HP;
                w = (jj < WCOLS) ? Wn[(size_t)(kt + k) * WCOLS + jj] : 0.0f;
            }
            Bs[k][j] = w;
        }
        __syncthreads();

        // --- compute ---
        #pragma unroll
        for (int kk = 0; kk < BK; kk++) {
            float4 av = *reinterpret_cast<const float4*>(&As[kk][trow * 4]);
            float a[4] = {av.x, av.y, av.z, av.w};
            float b[TN];
            #pragma unroll
            for (int c = 0; c < TN; c++)
                b[c] = Bs[kk][tcol + c * 16];
            #pragma unroll
            for (int r = 0; r < 4; r++)
                #pragma unroll
                for (int c = 0; c < TN; c++)
                    acc[r][c] += a[r] * b[c];
        }
        __syncthreads();
    }

    // --- epilogue: column j = tcol + c*16; j < HP -> S (+bias), else -> Y ---
    #pragma unroll
    for (int r = 0; r < 4; r++) {
        int gr = m0 + trow * 4 + r;
        if (gr < n) {
            #pragma unroll
            for (int c = 0; c < TN; c++) {
                int j = tcol + c * 16;
                if (j < HP) {
                    float bv = (j < WCOLS) ? bias[j] : 0.0f;
                    S[(size_t)gr * HP + j] = acc[r][c] + bv;
                } else {
                    Y[(size_t)gr * HP + (j - HP)] = acc[r][c];
                }
            }
        }
    }
}

// ---------------------------------------------------------------------------
// Edge scatter: for each edge e, S[dst[e]] += inv_deg[dst[e]] * Y[src[e]]
// One thread per float4 of the feature row. NV4 = feature_dim/4 (32 or 12).
// Uses vectorized no-return reduction red.global.add.v4.f32.
// ---------------------------------------------------------------------------
template<int NV4>
__global__ __launch_bounds__(256) void scatter_kernel(
    const float* __restrict__ Y, float* __restrict__ S,
    const int* __restrict__ src, const int* __restrict__ dst,
    const float* __restrict__ inv, int e)
{
    int idx = blockIdx.x * blockDim.x + threadIdx.x;
    int eid = idx / NV4;
    int c   = idx - eid * NV4;
    if (eid >= e) return;

    int s = src[eid];
    int d = dst[eid];
    float w = __ldg(inv + d);

    const float4 v = *reinterpret_cast<const float4*>(Y + (size_t)s * (NV4 * 4) + c * 4);
    float* p = S + (size_t)d * (NV4 * 4) + c * 4;
    asm volatile("red.global.add.v4.f32 [%0], {%1, %2, %3, %4};"
                 :: "l"(p), "f"(v.x * w), "f"(v.y * w), "f"(v.z * w), "f"(v.w * w)
                 : "memory");
}

// ---------------------------------------------------------------------------
__global__ void copy_out_kernel(const float* __restrict__ S, float* __restrict__ out, int n) {
    int idx = blockIdx.x * blockDim.x + threadIdx.x;
    int total = n * 47;
    if (idx < total) {
        int r = idx / 47;
        int c = idx - r * 47;
        out[idx] = S[(size_t)r * 48 + c];
    }
}

// ---------------------------------------------------------------------------
extern "C" void kernel_launch(void* const* d_in, const int* in_sizes, int n_in,
                              void* d_out, int out_size)
{
    const float* x   = (const float*)d_in[0];
    const int*   src = (const int*)d_in[1];
    const int*   dst = (const int*)d_in[2];
    const float* ws0 = (const float*)d_in[3];
    const float* wn0 = (const float*)d_in[4];
    const float* b0  = (const float*)d_in[5];
    const float* ws1 = (const float*)d_in[6];
    const float* wn1 = (const float*)d_in[7];
    const float* b1  = (const float*)d_in[8];
    const float* ws2 = (const float*)d_in[9];
    const float* wn2 = (const float*)d_in[10];
    const float* b2  = (const float*)d_in[11];
    float* out = (float*)d_out;

    const int n = in_sizes[0] / 128;   // 100000
    const int e = in_sizes[1];         // 1600000

    float *SA, *SB, *Yb, *inv;
    int* deg;
    cudaGetSymbolAddress((void**)&SA,  g_SA);
    cudaGetSymbolAddress((void**)&SB,  g_SB);
    cudaGetSymbolAddress((void**)&Yb,  g_Yb);
    cudaGetSymbolAddress((void**)&inv, g_inv);
    cudaGetSymbolAddress((void**)&deg, g_deg);

    // degrees (recomputed every call: deterministic, graph-capturable)
    deg_zero_kernel<<<(n + 255) / 256, 256>>>(deg, n);
    deg_count_kernel<<<(e + 255) / 256, 256>>>(deg, dst, e);
    deg_inv_kernel<<<(n + 255) / 256, 256>>>(deg, inv, n);

    const int gblocks = (n + 63) / 64;

    // Layer 0: x -> SA (self+bias), Yb (neigh-transformed); scatter into SA
    gemm_dual_kernel<128, 128, false><<<gblocks, 256>>>(x, n, ws0, wn0, b0, SA, Yb);
    scatter_kernel<32><<<(e * 32 + 255) / 256, 256>>>(Yb, SA, src, dst, inv, e);

    // Layer 1: relu(SA) -> SB, Yb; scatter into SB
    gemm_dual_kernel<128, 128, true><<<gblocks, 256>>>(SA, n, ws1, wn1, b1, SB, Yb);
    scatter_kernel<32><<<(e * 32 + 255) / 256, 256>>>(Yb, SB, src, dst, inv, e);

    // Layer 2: relu(SB) -> SA (stride 48, cols 0..46 valid), Yb (stride 48)
    gemm_dual_kernel<48, 47, true><<<gblocks, 256>>>(SB, n, ws2, wn2, b2, SA, Yb);
    scatter_kernel<12><<<(e * 12 + 255) / 256, 256>>>(Yb, SA, src, dst, inv, e);

    // strip 48 -> 47 padding into d_out
    copy_out_kernel<<<(n * 47 + 255) / 256, 256>>>(SA, out, n);
}

// round 2
// speedup vs baseline: 1.4076x; 1.4076x over previous
#include <cuda_runtime.h>
#include <cstdint>
#include <cstddef>

// ---------------------------------------------------------------------------
// GraphSAGE 3-layer forward, fp32, GB300 (sm_103a).
//   * transform-then-aggregate (aggregation is linear)
//   * dual-output GEMM with f32x2 packed FMA (fma.rn.f32x2) and low LDS ratio
//   * per-call CSR build, then gather-based aggregation (no atomics on features)
// ---------------------------------------------------------------------------

#define NMAX 100000
#define EMAX 1600000

// Scratch (static device globals: runtime allocation forbidden)
__device__ float g_SA[(size_t)NMAX * 128];
__device__ float g_SB[(size_t)NMAX * 128];
__device__ float g_Yb[(size_t)NMAX * 128];
__device__ float g_inv[NMAX];
__device__ int   g_deg[NMAX];
__device__ int   g_off[NMAX];
__device__ int   g_cur[NMAX];
__device__ int   g_csr[EMAX];
__device__ int   g_bsum[1024];
__device__ float g_W0[128 * 256];
__device__ float g_W1[128 * 256];
__device__ float g_W2[128 * 128];
__device__ float g_b0p[128];
__device__ float g_b1p[128];
__device__ float g_b2p[128];

// ---------------------------------------------------------------------------
// f32x2 helpers
// ---------------------------------------------------------------------------
__device__ __forceinline__ unsigned long long pk2(float x) {
    unsigned long long r;
    asm("mov.b64 %0, {%1, %1};" : "=l"(r) : "f"(x));
    return r;
}
__device__ __forceinline__ void ffma2(unsigned long long& d,
                                      unsigned long long a,
                                      unsigned long long b) {
    asm("fma.rn.f32x2 %0, %1, %2, %0;" : "+l"(d) : "l"(a), "l"(b));
}
__device__ __forceinline__ float2 upk(unsigned long long p) {
    float2 r;
    asm("mov.b64 {%0, %1}, %2;" : "=f"(r.x), "=f"(r.y) : "l"(p));
    return r;
}

// ---------------------------------------------------------------------------
// degree / inv
// ---------------------------------------------------------------------------
__global__ void deg_zero_kernel(int* __restrict__ deg, int n) {
    int i = blockIdx.x * blockDim.x + threadIdx.x;
    if (i < n) deg[i] = 0;
}
__global__ void deg_count_kernel(int* __restrict__ deg, const int* __restrict__ dst, int e) {
    int i = blockIdx.x * blockDim.x + threadIdx.x;
    if (i < e) atomicAdd(&deg[dst[i]], 1);
}
__global__ void deg_inv_kernel(const int* __restrict__ deg, float* __restrict__ inv, int n) {
    int i = blockIdx.x * blockDim.x + threadIdx.x;
    if (i < n) {
        int d = deg[i];
        inv[i] = 1.0f / (float)(d > 1 ? d : 1);
    }
}

// ---------------------------------------------------------------------------
// prefix scan (3-pass hierarchical) -> g_off (exclusive), g_cur = g_off copy
// ---------------------------------------------------------------------------
__global__ __launch_bounds__(1024) void scan1_kernel(
    const int* __restrict__ deg, int* __restrict__ off, int* __restrict__ bsum, int n)
{
    __shared__ int sh[1024];
    int t = threadIdx.x;
    int i = blockIdx.x * 1024 + t;
    int v = (i < n) ? deg[i] : 0;
    sh[t] = v;
    __syncthreads();
    #pragma unroll
    for (int s = 1; s < 1024; s <<= 1) {
        int x = (t >= s) ? sh[t - s] : 0;
        __syncthreads();
        sh[t] += x;
        __syncthreads();
    }
    if (i < n) off[i] = sh[t] - v;           // exclusive
    if (t == 1023) bsum[blockIdx.x] = sh[t]; // block total (inclusive)
}

__global__ __launch_bounds__(1024) void scan2_kernel(int* __restrict__ bsum, int nb) {
    __shared__ int sh[1024];
    int t = threadIdx.x;
    int v = (t < nb) ? bsum[t] : 0;
    sh[t] = v;
    __syncthreads();
    #pragma unroll
    for (int s = 1; s < 1024; s <<= 1) {
        int x = (t >= s) ? sh[t - s] : 0;
        __syncthreads();
        sh[t] += x;
        __syncthreads();
    }
    if (t < nb) bsum[t] = sh[t] - v;         // exclusive
}

__global__ void scan3_kernel(int* __restrict__ off, int* __restrict__ cur,
                             const int* __restrict__ bsum, int n) {
    int i = blockIdx.x * blockDim.x + threadIdx.x;
    if (i < n) {
        int o = off[i] + bsum[i >> 10];
        off[i] = o;
        cur[i] = o;
    }
}

__global__ void csr_fill_kernel(const int* __restrict__ src, const int* __restrict__ dst,
                                int* __restrict__ cur, int* __restrict__ csr, int e) {
    int i = blockIdx.x * blockDim.x + threadIdx.x;
    if (i < e) {
        int d = dst[i];
        int p = atomicAdd(&cur[d], 1);
        csr[p] = src[i];
    }
}

// ---------------------------------------------------------------------------
// weight pre-pack: Bp[k][j] = [Ws | Wn] padded to BN = 2*HPAD; bias padded.
// ---------------------------------------------------------------------------
__global__ void pack_w_kernel(const float* __restrict__ Ws, const float* __restrict__ Wn,
                              const float* __restrict__ b,
                              float* __restrict__ Bp, float* __restrict__ bp,
                              int WC, int HPAD) {
    int BN = 2 * HPAD;
    int idx = blockIdx.x * blockDim.x + threadIdx.x;
    if (idx < 128 * BN) {
        int k = idx / BN, j = idx - k * BN;
        float w = 0.0f;
        if (j < HPAD) { if (j < WC) w = Ws[k * WC + j]; }
        else          { int jj = j - HPAD; if (jj < WC) w = Wn[k * WC + jj]; }
        Bp[idx] = w;
    }
    if (idx < HPAD) bp[idx] = (idx < WC) ? b[idx] : 0.0f;
}

// ---------------------------------------------------------------------------
// Dual-output GEMM, f32x2 packed.
//   S[m, j] = (relu?)A[m,:] @ Ws[:, j] + bias[j]   (j < RS)
//   Y[m, j] = (relu?)A[m,:] @ Wn[:, j]             (j < RS)
// A: [n,128] row-major. Bp prepacked [128, BN], BN = 2*HPAD.
// Tile BM=64 x BN, BK=16, 256 threads. Each thread: 4 rows x (NG*4) cols,
// cols in NG groups of 4 at stride 64. Accumulators are f32x2 col-pairs.
// A tile stored duplicated as f32x2 -> inner loop is pure LDS.128 + FFMA2.
// ---------------------------------------------------------------------------
template<int HPAD, int RS, bool RELU>
__global__ __launch_bounds__(256) void gemm2_kernel(
    const float* __restrict__ A, int n,
    const float* __restrict__ Bp, const float* __restrict__ bp,
    float* __restrict__ S, float* __restrict__ Y)
{
    constexpr int BM = 64;
    constexpr int BK = 16;
    constexpr int K  = 128;
    constexpr int BN = 2 * HPAD;
    constexpr int NG = BN / 64;

    __shared__ unsigned long long As2[BK * BM];  // duplicated f32x2
    __shared__ float Bs[BK * BN];

    const int tid  = threadIdx.x;
    const int m0   = blockIdx.x * BM;
    const int tcol = tid & 15;
    const int trow = tid >> 4;

    unsigned long long acc[4][NG * 2];
    #pragma unroll
    for (int r = 0; r < 4; r++)
        #pragma unroll
        for (int c = 0; c < NG * 2; c++)
            acc[r][c] = 0ULL;

    const int lr = tid >> 2;        // loader row 0..63
    const int lk = (tid & 3) * 4;   // loader k-quad 0,4,8,12
    const int gr_load = m0 + lr;

    for (int kt = 0; kt < K; kt += BK) {
        // A tile -> duplicated f32x2, transposed
        float4 v = make_float4(0.f, 0.f, 0.f, 0.f);
        if (gr_load < n)
            v = *reinterpret_cast<const float4*>(A + (size_t)gr_load * K + kt + lk);
        if (RELU) {
            v.x = fmaxf(v.x, 0.f); v.y = fmaxf(v.y, 0.f);
            v.z = fmaxf(v.z, 0.f); v.w = fmaxf(v.w, 0.f);
        }
        As2[(lk + 0) * BM + lr] = pk2(v.x);
        As2[(lk + 1) * BM + lr] = pk2(v.y);
        As2[(lk + 2) * BM + lr] = pk2(v.z);
        As2[(lk + 3) * BM + lr] = pk2(v.w);

        // B tile (prepacked, float4)
        #pragma unroll
        for (int it = 0; it < (BK * BN) / 1024; it++) {
            int f  = tid + it * 256;
            int a4 = f * 4;
            int k  = a4 / BN;
            int j  = a4 - k * BN;
            *reinterpret_cast<float4*>(&Bs[a4]) =
                *reinterpret_cast<const float4*>(&Bp[(size_t)(kt + k) * BN + j]);
        }
        __syncthreads();

        #pragma unroll
        for (int kk = 0; kk < BK; kk++) {
            const ulonglong2* ap =
                reinterpret_cast<const ulonglong2*>(&As2[kk * BM + trow * 4]);
            ulonglong2 aA = ap[0];
            ulonglong2 aB = ap[1];
            unsigned long long ar[4] = {aA.x, aA.y, aB.x, aB.y};
            #pragma unroll
            for (int g = 0; g < NG; g++) {
                ulonglong2 b2 = *reinterpret_cast<const ulonglong2*>(
                    &Bs[kk * BN + g * 64 + tcol * 4]);
                #pragma unroll
                for (int r = 0; r < 4; r++) {
                    ffma2(acc[r][g * 2 + 0], ar[r], b2.x);
                    ffma2(acc[r][g * 2 + 1], ar[r], b2.y);
                }
            }
        }
        __syncthreads();
    }

    // epilogue
    #pragma unroll
    for (int r = 0; r < 4; r++) {
        int gr = m0 + trow * 4 + r;
        if (gr >= n) continue;
        #pragma unroll
        for (int g = 0; g < NG; g++) {
            int cb = g * 64 + tcol * 4;
            float2 lo = upk(acc[r][g * 2 + 0]);
            float2 hi = upk(acc[r][g * 2 + 1]);
            if (cb < HPAD) {
                if (cb < RS) {
                    float4 bb = *reinterpret_cast<const float4*>(&bp[cb]);
                    float4 o = make_float4(lo.x + bb.x, lo.y + bb.y,
                                           hi.x + bb.z, hi.y + bb.w);
                    *reinterpret_cast<float4*>(S + (size_t)gr * RS + cb) = o;
                }
            } else {
                int cb2 = cb - HPAD;
                if (cb2 < RS) {
                    *reinterpret_cast<float4*>(Y + (size_t)gr * RS + cb2) =
                        make_float4(lo.x, lo.y, hi.x, hi.y);
                }
            }
        }
    }
}

// ---------------------------------------------------------------------------
// Gather aggregation: one warp per node.
//   S[node] += inv[node] * sum_{e in-edges} Y[csr_src(e)]
// NV4 float4 lanes per row (32 for 128-wide, 12 for 48-wide).
// ---------------------------------------------------------------------------
template<int NV4, int RS>
__global__ __launch_bounds__(256) void agg_kernel(
    const float* __restrict__ Y, float* __restrict__ S,
    const int* __restrict__ csr, const int* __restrict__ off,
    const int* __restrict__ deg, const float* __restrict__ inv, int n)
{
    int w    = (blockIdx.x * blockDim.x + threadIdx.x) >> 5;
    int lane = threadIdx.x & 31;
    if (w >= n) return;
    if (lane >= NV4) return;

    int base = off[w];
    int dg   = deg[w];
    if (dg == 0) return;

    float4 a0 = make_float4(0.f, 0.f, 0.f, 0.f);
    float4 a1 = make_float4(0.f, 0.f, 0.f, 0.f);

    int i = 0;
    for (; i + 1 < dg; i += 2) {
        int s0 = __ldg(&csr[base + i]);
        int s1 = __ldg(&csr[base + i + 1]);
        float4 v0 = __ldg(reinterpret_cast<const float4*>(Y + (size_t)s0 * RS) + lane);
        float4 v1 = __ldg(reinterpret_cast<const float4*>(Y + (size_t)s1 * RS) + lane);
        a0.x += v0.x; a0.y += v0.y; a0.z += v0.z; a0.w += v0.w;
        a1.x += v1.x; a1.y += v1.y; a1.z += v1.z; a1.w += v1.w;
    }
    if (i < dg) {
        int s0 = __ldg(&csr[base + i]);
        float4 v0 = __ldg(reinterpret_cast<const float4*>(Y + (size_t)s0 * RS) + lane);
        a0.x += v0.x; a0.y += v0.y; a0.z += v0.z; a0.w += v0.w;
    }

    float iv = __ldg(&inv[w]);
    float4* sp = reinterpret_cast<float4*>(S + (size_t)w * RS) + lane;
    float4 cur = *sp;
    cur.x += iv * (a0.x + a1.x);
    cur.y += iv * (a0.y + a1.y);
    cur.z += iv * (a0.z + a1.z);
    cur.w += iv * (a0.w + a1.w);
    *sp = cur;
}

// ---------------------------------------------------------------------------
__global__ void copy_out_kernel(const float* __restrict__ S, float* __restrict__ out, int n) {
    int idx = blockIdx.x * blockDim.x + threadIdx.x;
    int total = n * 47;
    if (idx < total) {
        int r = idx / 47;
        int c = idx - r * 47;
        out[idx] = S[(size_t)r * 48 + c];
    }
}

// ---------------------------------------------------------------------------
extern "C" void kernel_launch(void* const* d_in, const int* in_sizes, int n_in,
                              void* d_out, int out_size)
{
    const float* x   = (const float*)d_in[0];
    const int*   src = (const int*)d_in[1];
    const int*   dst = (const int*)d_in[2];
    const float* ws0 = (const float*)d_in[3];
    const float* wn0 = (const float*)d_in[4];
    const float* b0  = (const float*)d_in[5];
    const float* ws1 = (const float*)d_in[6];
    const float* wn1 = (const float*)d_in[7];
    const float* b1  = (const float*)d_in[8];
    const float* ws2 = (const float*)d_in[9];
    const float* wn2 = (const float*)d_in[10];
    const float* b2  = (const float*)d_in[11];
    float* out = (float*)d_out;

    const int n = in_sizes[0] / 128;   // 100000
    const int e = in_sizes[1];         // 1600000

    float *SA, *SB, *Yb, *inv, *W0, *W1, *W2, *b0p, *b1p, *b2p;
    int *deg, *off, *cur, *csr, *bsum;
    cudaGetSymbolAddress((void**)&SA,   g_SA);
    cudaGetSymbolAddress((void**)&SB,   g_SB);
    cudaGetSymbolAddress((void**)&Yb,   g_Yb);
    cudaGetSymbolAddress((void**)&inv,  g_inv);
    cudaGetSymbolAddress((void**)&deg,  g_deg);
    cudaGetSymbolAddress((void**)&off,  g_off);
    cudaGetSymbolAddress((void**)&cur,  g_cur);
    cudaGetSymbolAddress((void**)&csr,  g_csr);
    cudaGetSymbolAddress((void**)&bsum, g_bsum);
    cudaGetSymbolAddress((void**)&W0,   g_W0);
    cudaGetSymbolAddress((void**)&W1,   g_W1);
    cudaGetSymbolAddress((void**)&W2,   g_W2);
    cudaGetSymbolAddress((void**)&b0p,  g_b0p);
    cudaGetSymbolAddress((void**)&b1p,  g_b1p);
    cudaGetSymbolAddress((void**)&b2p,  g_b2p);

    // --- graph structure (once per call) ---
    deg_zero_kernel<<<(n + 255) / 256, 256>>>(deg, n);
    deg_count_kernel<<<(e + 255) / 256, 256>>>(deg, dst, e);
    deg_inv_kernel<<<(n + 255) / 256, 256>>>(deg, inv, n);

    int nb = (n + 1023) / 1024;
    scan1_kernel<<<nb, 1024>>>(deg, off, bsum, n);
    scan2_kernel<<<1, 1024>>>(bsum, nb);
    scan3_kernel<<<(n + 255) / 256, 256>>>(off, cur, bsum, n);
    csr_fill_kernel<<<(e + 255) / 256, 256>>>(src, dst, cur, csr, e);

    // --- weight prepack ---
    pack_w_kernel<<<(128 * 256 + 255) / 256, 256>>>(ws0, wn0, b0, W0, b0p, 128, 128);
    pack_w_kernel<<<(128 * 256 + 255) / 256, 256>>>(ws1, wn1, b1, W1, b1p, 128, 128);
    pack_w_kernel<<<(128 * 128 + 255) / 256, 256>>>(ws2, wn2, b2, W2, b2p, 47, 64);

    const int gblocks = (n + 63) / 64;
    const int ablocks = (n * 32 + 255) / 256;

    // Layer 0
    gemm2_kernel<128, 128, false><<<gblocks, 256>>>(x, n, W0, b0p, SA, Yb);
    agg_kernel<32, 128><<<ablocks, 256>>>(Yb, SA, csr, off, deg, inv, n);

    // Layer 1
    gemm2_kernel<128, 128, true><<<gblocks, 256>>>(SA, n, W1, b1p, SB, Yb);
    agg_kernel<32, 128><<<ablocks, 256>>>(Yb, SB, csr, off, deg, inv, n);

    // Layer 2 (padded BN=128; storage stride 48)
    gemm2_kernel<64, 48, true><<<gblocks, 256>>>(SB, n, W2, b2p, SA, Yb);
    agg_kernel<12, 48><<<ablocks, 256>>>(Yb, SA, csr, off, deg, inv, n);

    copy_out_kernel<<<(n * 47 + 255) / 256, 256>>>(SA, out, n);
}